// round 2
// baseline (speedup 1.0000x reference)
#include <cuda_runtime.h>
#include <cuda_bf16.h>

#define N_NODES 100000
#define N_EDGES 600000
#define HID 128

// Scratch (device globals: no allocation allowed in kernel_launch)
__device__ float g_deg[N_NODES];
__device__ float g_dinv[N_NODES];
__device__ float g_aggx[(size_t)N_NODES * HID];

// ---------------------------------------------------------------------------
// K1: deg init to 1.0 (self-loop folded in)
// ---------------------------------------------------------------------------
__global__ void k_init_deg() {
    int i = blockIdx.x * blockDim.x + threadIdx.x;
    if (i < N_NODES) g_deg[i] = 1.0f;
}

// ---------------------------------------------------------------------------
// K2: in-degree scatter count
// ---------------------------------------------------------------------------
__global__ void k_deg(const int* __restrict__ dst) {
    int e = blockIdx.x * blockDim.x + threadIdx.x;
    if (e < N_EDGES) atomicAdd(&g_deg[dst[e]], 1.0f);
}

// ---------------------------------------------------------------------------
// K3: dinv = rsqrt(deg); agg_x init = x * dinv^2  (self-loop contribution)
// one thread per float4 of x
// ---------------------------------------------------------------------------
__global__ void k_dinv_agginit(const float4* __restrict__ x4) {
    int idx = blockIdx.x * blockDim.x + threadIdx.x;
    if (idx >= N_NODES * (HID / 4)) return;
    int node = idx >> 5;               // 32 float4 per row
    float r = rsqrtf(g_deg[node]);
    if ((idx & 31) == 0) g_dinv[node] = r;
    float s = r * r;
    float4 v = x4[idx];
    v.x *= s; v.y *= s; v.z *= s; v.w *= s;
    ((float4*)g_aggx)[idx] = v;
}

// ---------------------------------------------------------------------------
// K4: edge scatter. One warp per edge; lane l handles float4 l of the row.
// agg_x[dst] += norm * x[src] via vector reduction (red.global.add.v4.f32).
// ---------------------------------------------------------------------------
__global__ void k_scatter(const int* __restrict__ src, const int* __restrict__ dst,
                          const float4* __restrict__ x4) {
    int gt = blockIdx.x * blockDim.x + threadIdx.x;
    int e = gt >> 5;
    int lane = threadIdx.x & 31;
    if (e >= N_EDGES) return;
    int s = src[e];
    int d = dst[e];
    float norm = g_dinv[s] * g_dinv[d];
    float4 v = x4[s * (HID / 4) + lane];
    float4* p = ((float4*)g_aggx) + (size_t)d * (HID / 4) + lane;
    asm volatile("red.global.add.v4.f32 [%0], {%1, %2, %3, %4};"
                 :: "l"(p), "f"(v.x * norm), "f"(v.y * norm),
                    "f"(v.z * norm), "f"(v.w * norm)
                 : "memory");
}

// ---------------------------------------------------------------------------
// K5: fused  out = LN( relu(agg_x @ W + b) + x ) * gamma + beta
// Block: 256 threads, tile = 64 rows x 128 cols (full row -> LN fusable).
// Micro-tile 4 rows x 8 cols per thread. W + k-major A tile in dynamic smem.
// Row r's 128 cols live in 16 consecutive lanes -> shfl_xor(width=16) LN reduce.
// ---------------------------------------------------------------------------
__global__ void __launch_bounds__(256, 2)
k_gemm_ln(const float* __restrict__ W,
          const float* __restrict__ bias,
          const float* __restrict__ gamma,
          const float* __restrict__ beta,
          const float* __restrict__ x,
          float* __restrict__ out) {
    extern __shared__ float smf[];
    float* Ws = smf;               // [128][128], row k major
    float* As = smf + HID * HID;   // [128][64],  As[k*64+m]

    int tid = threadIdx.x;
    int rowBase = blockIdx.x * 64;

    // Load W (64 KB), straight copy, float4
    {
        const float4* W4 = (const float4*)W;
        float4* Ws4 = (float4*)Ws;
        #pragma unroll
        for (int i = tid; i < HID * HID / 4; i += 256) Ws4[i] = W4[i];
    }

    // Load A tile transposed: As[k*64+m] = agg_x[rowBase+m][k]
    {
        const float4* A4 = (const float4*)g_aggx;
        for (int i = tid; i < 64 * (HID / 4); i += 256) {
            int m = i & 63;
            int k4 = i >> 6;   // 0..31
            int row = rowBase + m;
            float4 v = make_float4(0.f, 0.f, 0.f, 0.f);
            if (row < N_NODES) v = A4[(size_t)row * (HID / 4) + k4];
            As[(k4 * 4 + 0) * 64 + m] = v.x;
            As[(k4 * 4 + 1) * 64 + m] = v.y;
            As[(k4 * 4 + 2) * 64 + m] = v.z;
            As[(k4 * 4 + 3) * 64 + m] = v.w;
        }
    }
    __syncthreads();

    int tn = tid & 15;   // col group: cols tn*8 .. tn*8+7
    int tm = tid >> 4;   // row group: rows tm*4 .. tm*4+3

    float acc[4][8];
    #pragma unroll
    for (int i = 0; i < 4; i++)
        #pragma unroll
        for (int j = 0; j < 8; j++) acc[i][j] = 0.f;

    #pragma unroll 4
    for (int k = 0; k < HID; k++) {
        float4 a  = *(const float4*)&As[k * 64 + tm * 4];
        float4 b0 = *(const float4*)&Ws[k * HID + tn * 8];
        float4 b1 = *(const float4*)&Ws[k * HID + tn * 8 + 4];
        float av[4] = {a.x, a.y, a.z, a.w};
        float bv[8] = {b0.x, b0.y, b0.z, b0.w, b1.x, b1.y, b1.z, b1.w};
        #pragma unroll
        for (int i = 0; i < 4; i++)
            #pragma unroll
            for (int j = 0; j < 8; j++)
                acc[i][j] = fmaf(av[i], bv[j], acc[i][j]);
    }

    int c0 = tn * 8;
    float bb[8], gg[8], be[8];
    {
        float4 t0 = *(const float4*)&bias[c0],  t1 = *(const float4*)&bias[c0 + 4];
        bb[0]=t0.x; bb[1]=t0.y; bb[2]=t0.z; bb[3]=t0.w; bb[4]=t1.x; bb[5]=t1.y; bb[6]=t1.z; bb[7]=t1.w;
        float4 g0 = *(const float4*)&gamma[c0], g1 = *(const float4*)&gamma[c0 + 4];
        gg[0]=g0.x; gg[1]=g0.y; gg[2]=g0.z; gg[3]=g0.w; gg[4]=g1.x; gg[5]=g1.y; gg[6]=g1.z; gg[7]=g1.w;
        float4 e0 = *(const float4*)&beta[c0],  e1 = *(const float4*)&beta[c0 + 4];
        be[0]=e0.x; be[1]=e0.y; be[2]=e0.z; be[3]=e0.w; be[4]=e1.x; be[5]=e1.y; be[6]=e1.z; be[7]=e1.w;
    }

    #pragma unroll
    for (int i = 0; i < 4; i++) {
        int row = rowBase + tm * 4 + i;
        bool valid = row < N_NODES;
        int rowc = valid ? row : 0;

        const float4* xr = (const float4*)&x[(size_t)rowc * HID + c0];
        float4 x0 = xr[0], x1 = xr[1];
        float xv[8] = {x0.x, x0.y, x0.z, x0.w, x1.x, x1.y, x1.z, x1.w};

        float v[8];
        float sum = 0.f, sq = 0.f;
        #pragma unroll
        for (int j = 0; j < 8; j++) {
            float t = fmaxf(acc[i][j] + bb[j], 0.f) + xv[j];
            v[j] = t;
            sum += t;
            sq  += t * t;
        }
        // LN reduce over the 16 lanes holding this row
        #pragma unroll
        for (int off = 8; off > 0; off >>= 1) {
            sum += __shfl_xor_sync(0xffffffffu, sum, off, 16);
            sq  += __shfl_xor_sync(0xffffffffu, sq,  off, 16);
        }
        float mu   = sum * (1.f / HID);
        float var  = sq * (1.f / HID) - mu * mu;
        float rstd = rsqrtf(var + 1e-8f);

        if (valid) {
            float o[8];
            #pragma unroll
            for (int j = 0; j < 8; j++)
                o[j] = (v[j] - mu) * rstd * gg[j] + be[j];
            float4* op = (float4*)&out[(size_t)row * HID + c0];
            op[0] = make_float4(o[0], o[1], o[2], o[3]);
            op[1] = make_float4(o[4], o[5], o[6], o[7]);
        }
    }
}

// ---------------------------------------------------------------------------
extern "C" void kernel_launch(void* const* d_in, const int* in_sizes, int n_in,
                              void* d_out, int out_size) {
    const float* x     = (const float*)d_in[0];
    const int*   ei    = (const int*)d_in[1];
    const float* W     = (const float*)d_in[2];
    const float* b     = (const float*)d_in[3];
    const float* gamma = (const float*)d_in[4];
    const float* beta  = (const float*)d_in[5];
    float* out = (float*)d_out;

    const int* src = ei;             // edge_index[0]
    const int* dst = ei + N_EDGES;   // edge_index[1]

    k_init_deg<<<(N_NODES + 255) / 256, 256>>>();
    k_deg<<<(N_EDGES + 255) / 256, 256>>>(dst);
    k_dinv_agginit<<<(N_NODES * (HID / 4) + 255) / 256, 256>>>((const float4*)x);
    {
        long long threads = (long long)N_EDGES * 32;
        int blocks = (int)((threads + 255) / 256);
        k_scatter<<<blocks, 256>>>(src, dst, (const float4*)x);
    }
    cudaFuncSetAttribute(k_gemm_ln, cudaFuncAttributeMaxDynamicSharedMemorySize,
                         (HID * HID + HID * 64) * sizeof(float));
    k_gemm_ln<<<(N_NODES + 63) / 64, 256, (HID * HID + HID * 64) * sizeof(float)>>>(
        W, b, gamma, beta, x, out);
}

// round 3
// speedup vs baseline: 1.0415x; 1.0415x over previous
#include <cuda_runtime.h>
#include <cuda_bf16.h>

#define N_NODES 100000
#define N_EDGES 600000
#define HID 128
#define SCAN_BLK 2048
#define NPART ((N_NODES + SCAN_BLK - 1) / SCAN_BLK)   // 49

typedef unsigned long long u64;

// Scratch (device globals: no allocation allowed in kernel_launch)
__device__ int   g_degi[N_NODES];
__device__ int   g_off[N_NODES + 1];
__device__ int   g_pos[N_NODES];
__device__ int   g_csr[N_EDGES];
__device__ int   g_part[NPART];
__device__ float g_dinv[N_NODES];

// ---------------------------------------------------------------------------
__global__ void k_zero() {
    int i = blockIdx.x * blockDim.x + threadIdx.x;
    if (i < N_NODES) g_degi[i] = 0;
}

__global__ void k_count(const int* __restrict__ dst) {
    int e = blockIdx.x * blockDim.x + threadIdx.x;
    if (e < N_EDGES) atomicAdd(&g_degi[dst[e]], 1);
}

// ---------------------------------------------------------------------------
// Scan over degi -> exclusive offsets (3 kernels)
// ---------------------------------------------------------------------------
__global__ void k_scan1() {   // per-block totals
    __shared__ int wsum[8];
    int b = blockIdx.x, t = threadIdx.x;
    int base = b * SCAN_BLK + t * 8;
    int s = 0;
    #pragma unroll
    for (int j = 0; j < 8; j++) {
        int i = base + j;
        s += (i < N_NODES) ? g_degi[i] : 0;
    }
    #pragma unroll
    for (int o = 16; o > 0; o >>= 1) s += __shfl_down_sync(~0u, s, o);
    if ((t & 31) == 0) wsum[t >> 5] = s;
    __syncthreads();
    if (t == 0) {
        int tot = 0;
        #pragma unroll
        for (int w = 0; w < 8; w++) tot += wsum[w];
        g_part[b] = tot;
    }
}

__global__ void k_scan2() {   // exclusive scan of 49 partials (serial, tiny)
    if (threadIdx.x == 0) {
        int acc = 0;
        for (int i = 0; i < NPART; i++) { int v = g_part[i]; g_part[i] = acc; acc += v; }
        g_off[N_NODES] = N_EDGES;
    }
}

__global__ void k_scan3() {   // full exclusive scan + pos init + dinv
    __shared__ int woff[8];
    int b = blockIdx.x, t = threadIdx.x;
    int lane = t & 31, warp = t >> 5;
    int base = b * SCAN_BLK + t * 8;
    int v[8];
    int s = 0;
    #pragma unroll
    for (int j = 0; j < 8; j++) {
        int i = base + j;
        v[j] = (i < N_NODES) ? g_degi[i] : 0;
        s += v[j];
    }
    int sc = s;   // inclusive scan within warp
    #pragma unroll
    for (int o = 1; o < 32; o <<= 1) {
        int u = __shfl_up_sync(~0u, sc, o);
        if (lane >= o) sc += u;
    }
    if (lane == 31) woff[warp] = sc;
    __syncthreads();
    if (t == 0) {
        int acc = 0;
        #pragma unroll
        for (int w = 0; w < 8; w++) { int x = woff[w]; woff[w] = acc; acc += x; }
    }
    __syncthreads();
    int run = g_part[b] + woff[warp] + (sc - s);   // exclusive prefix
    #pragma unroll
    for (int j = 0; j < 8; j++) {
        int i = base + j;
        if (i < N_NODES) {
            g_off[i] = run;
            g_pos[i] = run;
            g_dinv[i] = rsqrtf((float)(1 + v[j]));
            run += v[j];
        }
    }
}

__global__ void k_fill(const int* __restrict__ src, const int* __restrict__ dst) {
    int e = blockIdx.x * blockDim.x + threadIdx.x;
    if (e < N_EDGES) {
        int p = atomicAdd(&g_pos[dst[e]], 1);
        g_csr[p] = src[e];
    }
}

// ---------------------------------------------------------------------------
// Packed f32x2 helpers (SASS FFMA2 — only reachable via PTX fma.rn.f32x2)
// ---------------------------------------------------------------------------
__device__ __forceinline__ u64 pack2(float v) {
    u64 r;
    asm("mov.b64 %0, {%1, %1};" : "=l"(r) : "f"(v));
    return r;
}
__device__ __forceinline__ void fma2(u64& d, u64 a, u64 b) {
    asm("fma.rn.f32x2 %0, %1, %2, %3;" : "=l"(d) : "l"(a), "l"(b), "l"(d));
}
__device__ __forceinline__ void unpack2(u64 v, float& lo, float& hi) {
    asm("mov.b64 {%0, %1}, %2;" : "=f"(lo), "=f"(hi) : "l"(v));
}

// ---------------------------------------------------------------------------
// Fused: gather(CSR) -> smem A tile -> GEMM(f32x2) -> bias/ReLU/res/LayerNorm
// Block: 256 threads, 64 rows x 128 cols. smem: W 64KB + A^T 32KB.
// ---------------------------------------------------------------------------
__global__ void __launch_bounds__(256, 2)
k_fused(const float* __restrict__ W,
        const float* __restrict__ bias,
        const float* __restrict__ gamma,
        const float* __restrict__ beta,
        const float* __restrict__ x,
        float* __restrict__ out) {
    extern __shared__ float smf[];
    float* Ws = smf;               // [128][128] k-major
    float* As = smf + HID * HID;   // [128][64]  As[k*64+m]

    const float4* x4 = (const float4*)x;
    int tid = threadIdx.x;
    int lane = tid & 31, warp = tid >> 5;
    int rowBase = blockIdx.x * 64;

    // ---- Load W
    {
        const float4* W4 = (const float4*)W;
        float4* Ws4 = (float4*)Ws;
        #pragma unroll
        for (int i = tid; i < HID * HID / 4; i += 256) Ws4[i] = W4[i];
    }

    // ---- Gather phase: warp w handles rows w*8 .. w*8+7
    #pragma unroll
    for (int j = 0; j < 8; j++) {
        int m = warp * 8 + j;
        int node = rowBase + m;
        float4 acc = make_float4(0.f, 0.f, 0.f, 0.f);
        if (node < N_NODES) {
            float di = g_dinv[node];
            float4 v = x4[node * (HID / 4) + lane];
            float s2 = di * di;                       // self-loop norm
            acc.x = v.x * s2; acc.y = v.y * s2; acc.z = v.z * s2; acc.w = v.w * s2;
            int e0 = g_off[node], e1 = g_off[node + 1];
            int e = e0;
            while (e < e1) {
                int cnt = min(e1 - e, 32);
                int s_l = (lane < cnt) ? g_csr[e + lane] : 0;
                float n_l = (lane < cnt) ? g_dinv[s_l] * di : 0.f;
                for (int q = 0; q < cnt; q++) {
                    int s = __shfl_sync(~0u, s_l, q);
                    float nm = __shfl_sync(~0u, n_l, q);
                    float4 xv = x4[s * (HID / 4) + lane];
                    acc.x = fmaf(xv.x, nm, acc.x);
                    acc.y = fmaf(xv.y, nm, acc.y);
                    acc.z = fmaf(xv.z, nm, acc.z);
                    acc.w = fmaf(xv.w, nm, acc.w);
                }
                e += cnt;
            }
        }
        // transpose into As: lane l holds k = l*4 .. l*4+3
        As[(lane * 4 + 0) * 64 + m] = acc.x;
        As[(lane * 4 + 1) * 64 + m] = acc.y;
        As[(lane * 4 + 2) * 64 + m] = acc.z;
        As[(lane * 4 + 3) * 64 + m] = acc.w;
    }
    __syncthreads();

    // ---- GEMM: micro-tile 4 rows x 8 cols, packed f32x2 accumulators
    int tn = tid & 15;   // cols tn*8 .. +7
    int tm = tid >> 4;   // rows tm*4 .. +3

    u64 acc2[4][4];
    #pragma unroll
    for (int i = 0; i < 4; i++)
        #pragma unroll
        for (int jj = 0; jj < 4; jj++) acc2[i][jj] = 0ull;

    #pragma unroll 4
    for (int k = 0; k < HID; k++) {
        float4 a = *(const float4*)&As[k * 64 + tm * 4];
        const u64* wrow = (const u64*)&Ws[k * HID + tn * 8];
        u64 b0 = wrow[0], b1 = wrow[1], b2 = wrow[2], b3 = wrow[3];
        u64 a0 = pack2(a.x), a1 = pack2(a.y), a2 = pack2(a.z), a3 = pack2(a.w);
        fma2(acc2[0][0], a0, b0); fma2(acc2[0][1], a0, b1);
        fma2(acc2[0][2], a0, b2); fma2(acc2[0][3], a0, b3);
        fma2(acc2[1][0], a1, b0); fma2(acc2[1][1], a1, b1);
        fma2(acc2[1][2], a1, b2); fma2(acc2[1][3], a1, b3);
        fma2(acc2[2][0], a2, b0); fma2(acc2[2][1], a2, b1);
        fma2(acc2[2][2], a2, b2); fma2(acc2[2][3], a2, b3);
        fma2(acc2[3][0], a3, b0); fma2(acc2[3][1], a3, b1);
        fma2(acc2[3][2], a3, b2); fma2(acc2[3][3], a3, b3);
    }

    // ---- Epilogue: bias, ReLU, residual, LayerNorm (16-lane shuffle reduce)
    int c0 = tn * 8;
    float bb[8], gg[8], be[8];
    {
        float4 t0 = *(const float4*)&bias[c0],  t1 = *(const float4*)&bias[c0 + 4];
        bb[0]=t0.x; bb[1]=t0.y; bb[2]=t0.z; bb[3]=t0.w; bb[4]=t1.x; bb[5]=t1.y; bb[6]=t1.z; bb[7]=t1.w;
        float4 g0 = *(const float4*)&gamma[c0], g1 = *(const float4*)&gamma[c0 + 4];
        gg[0]=g0.x; gg[1]=g0.y; gg[2]=g0.z; gg[3]=g0.w; gg[4]=g1.x; gg[5]=g1.y; gg[6]=g1.z; gg[7]=g1.w;
        float4 e0 = *(const float4*)&beta[c0],  e1 = *(const float4*)&beta[c0 + 4];
        be[0]=e0.x; be[1]=e0.y; be[2]=e0.z; be[3]=e0.w; be[4]=e1.x; be[5]=e1.y; be[6]=e1.z; be[7]=e1.w;
    }

    #pragma unroll
    for (int i = 0; i < 4; i++) {
        int row = rowBase + tm * 4 + i;
        bool valid = row < N_NODES;
        int rowc = valid ? row : 0;

        float av[8];
        #pragma unroll
        for (int jj = 0; jj < 4; jj++) unpack2(acc2[i][jj], av[2 * jj], av[2 * jj + 1]);

        const float4* xr = (const float4*)&x[(size_t)rowc * HID + c0];
        float4 x0 = xr[0], x1 = xr[1];
        float xv[8] = {x0.x, x0.y, x0.z, x0.w, x1.x, x1.y, x1.z, x1.w};

        float v[8];
        float sum = 0.f, sq = 0.f;
        #pragma unroll
        for (int j = 0; j < 8; j++) {
            float t = fmaxf(av[j] + bb[j], 0.f) + xv[j];
            v[j] = t;
            sum += t;
            sq  += t * t;
        }
        #pragma unroll
        for (int off = 8; off > 0; off >>= 1) {
            sum += __shfl_xor_sync(0xffffffffu, sum, off, 16);
            sq  += __shfl_xor_sync(0xffffffffu, sq,  off, 16);
        }
        float mu   = sum * (1.f / HID);
        float var  = sq * (1.f / HID) - mu * mu;
        float rstd = rsqrtf(var + 1e-8f);

        if (valid) {
            float o[8];
            #pragma unroll
            for (int j = 0; j < 8; j++)
                o[j] = (v[j] - mu) * rstd * gg[j] + be[j];
            float4* op = (float4*)&out[(size_t)row * HID + c0];
            op[0] = make_float4(o[0], o[1], o[2], o[3]);
            op[1] = make_float4(o[4], o[5], o[6], o[7]);
        }
    }
}

// ---------------------------------------------------------------------------
extern "C" void kernel_launch(void* const* d_in, const int* in_sizes, int n_in,
                              void* d_out, int out_size) {
    const float* x     = (const float*)d_in[0];
    const int*   ei    = (const int*)d_in[1];
    const float* W     = (const float*)d_in[2];
    const float* b     = (const float*)d_in[3];
    const float* gamma = (const float*)d_in[4];
    const float* beta  = (const float*)d_in[5];
    float* out = (float*)d_out;

    const int* src = ei;             // edge_index[0]
    const int* dst = ei + N_EDGES;   // edge_index[1]

    k_zero<<<(N_NODES + 255) / 256, 256>>>();
    k_count<<<(N_EDGES + 255) / 256, 256>>>(dst);
    k_scan1<<<NPART, 256>>>();
    k_scan2<<<1, 32>>>();
    k_scan3<<<NPART, 256>>>();
    k_fill<<<(N_EDGES + 255) / 256, 256>>>(src, dst);

    static int smem_set = 0;
    int smem = (HID * HID + HID * 64) * sizeof(float);
    if (!smem_set) {
        cudaFuncSetAttribute(k_fused, cudaFuncAttributeMaxDynamicSharedMemorySize, smem);
        smem_set = 1;
    }
    k_fused<<<(N_NODES + 63) / 64, 256, smem>>>(W, b, gamma, beta, x, out);
}

// round 4
// speedup vs baseline: 1.0870x; 1.0436x over previous
#include <cuda_runtime.h>
#include <cuda_bf16.h>

#define N_NODES 100000
#define N_EDGES 600000
#define HID 128

typedef unsigned long long u64;

// Scratch (device globals: no allocation allowed in kernel_launch)
__device__ int   g_degi[N_NODES];
__device__ int   g_off[N_NODES];
__device__ int   g_end[N_NODES];
__device__ int   g_pos[N_NODES];
__device__ int   g_csr[N_EDGES];
__device__ int   g_cursor;
__device__ float g_dinv[N_NODES];

// ---------------------------------------------------------------------------
// K1: in-degree count (g_degi zeroed by cudaMemsetAsync)
// ---------------------------------------------------------------------------
__global__ void k_count(const int* __restrict__ dst) {
    int e = blockIdx.x * blockDim.x + threadIdx.x;
    if (e < N_EDGES) atomicAdd(&g_degi[dst[e]], 1);
}

// ---------------------------------------------------------------------------
// K2: slot allocation via warp-aggregated atomic cursor (CSR range order is
// irrelevant — only contiguity per node matters). Also writes dinv.
// ---------------------------------------------------------------------------
__global__ void k_alloc() {
    int i = blockIdx.x * blockDim.x + threadIdx.x;
    int lane = threadIdx.x & 31;
    bool valid = i < N_NODES;
    int d = valid ? g_degi[i] : 0;
    int sc = d;   // inclusive warp scan
    #pragma unroll
    for (int o = 1; o < 32; o <<= 1) {
        int u = __shfl_up_sync(~0u, sc, o);
        if (lane >= o) sc += u;
    }
    int total = __shfl_sync(~0u, sc, 31);
    int base = 0;
    if (lane == 31) base = atomicAdd(&g_cursor, total);
    base = __shfl_sync(~0u, base, 31);
    int off = base + sc - d;   // exclusive
    if (valid) {
        g_off[i] = off;
        g_pos[i] = off;
        g_end[i] = off + d;
        g_dinv[i] = rsqrtf((float)(1 + d));
    }
}

// ---------------------------------------------------------------------------
// K3: CSR fill
// ---------------------------------------------------------------------------
__global__ void k_fill(const int* __restrict__ src, const int* __restrict__ dst) {
    int e = blockIdx.x * blockDim.x + threadIdx.x;
    if (e < N_EDGES) {
        int p = atomicAdd(&g_pos[dst[e]], 1);
        g_csr[p] = src[e];
    }
}

// ---------------------------------------------------------------------------
// Packed f32x2 helpers (SASS FFMA2 — only reachable via PTX fma.rn.f32x2)
// ---------------------------------------------------------------------------
__device__ __forceinline__ u64 pack2(float v) {
    u64 r;
    asm("mov.b64 %0, {%1, %1};" : "=l"(r) : "f"(v));
    return r;
}
__device__ __forceinline__ void fma2(u64& d, u64 a, u64 b) {
    asm("fma.rn.f32x2 %0, %1, %2, %3;" : "=l"(d) : "l"(a), "l"(b), "l"(d));
}
__device__ __forceinline__ void unpack2(u64 v, float& lo, float& hi) {
    asm("mov.b64 {%0, %1}, %2;" : "=f"(lo), "=f"(hi) : "l"(v));
}

// ---------------------------------------------------------------------------
// Fused: gather(CSR, MLP-4) -> smem A -> GEMM(f32x2) -> bias/ReLU/res/LN
// Block 256 threads, tile 64 rows x 128 cols. smem: W 64KB + A^T 32KB.
// ---------------------------------------------------------------------------
__global__ void __launch_bounds__(256, 2)
k_fused(const float* __restrict__ W,
        const float* __restrict__ bias,
        const float* __restrict__ gamma,
        const float* __restrict__ beta,
        const float* __restrict__ x,
        float* __restrict__ out) {
    extern __shared__ float smf[];
    float* Ws = smf;               // [128][128] k-major
    float* As = smf + HID * HID;   // [128][64]  As[k*64+m]

    const float4* x4 = (const float4*)x;
    int tid = threadIdx.x;
    int lane = tid & 31, warp = tid >> 5;
    int rowBase = blockIdx.x * 64;

    // ---- Load W (64 KB)
    {
        const float4* W4 = (const float4*)W;
        float4* Ws4 = (float4*)Ws;
        #pragma unroll
        for (int i = tid; i < HID * HID / 4; i += 256) Ws4[i] = W4[i];
    }

    // ---- Gather: warp w handles rows w*8 .. w*8+7; lane owns float4 slice
    #pragma unroll
    for (int j = 0; j < 8; j++) {
        int m = warp * 8 + j;
        int node = rowBase + m;
        float4 acc = make_float4(0.f, 0.f, 0.f, 0.f);
        if (node < N_NODES) {
            float di = g_dinv[node];
            float4 v = x4[node * (HID / 4) + lane];
            float s2 = di * di;                       // self-loop norm
            acc.x = v.x * s2; acc.y = v.y * s2; acc.z = v.z * s2; acc.w = v.w * s2;
            int e = g_off[node], e1 = g_end[node];
            while (e < e1) {
                int cnt = min(e1 - e, 32);
                int s_l = (lane < cnt) ? g_csr[e + lane] : 0;
                float n_l = (lane < cnt) ? g_dinv[s_l] * di : 0.f;
                int cntR = (cnt + 3) & ~3;            // lanes >= cnt carry norm 0
                for (int q = 0; q < cntR; q += 4) {
                    int s0 = __shfl_sync(~0u, s_l, q + 0);
                    int s1 = __shfl_sync(~0u, s_l, q + 1);
                    int s2i = __shfl_sync(~0u, s_l, q + 2);
                    int s3 = __shfl_sync(~0u, s_l, q + 3);
                    float m0 = __shfl_sync(~0u, n_l, q + 0);
                    float m1 = __shfl_sync(~0u, n_l, q + 1);
                    float m2 = __shfl_sync(~0u, n_l, q + 2);
                    float m3 = __shfl_sync(~0u, n_l, q + 3);
                    // 4 independent loads in flight before any consumer
                    float4 v0 = x4[s0 * (HID / 4) + lane];
                    float4 v1 = x4[s1 * (HID / 4) + lane];
                    float4 v2 = x4[s2i * (HID / 4) + lane];
                    float4 v3 = x4[s3 * (HID / 4) + lane];
                    acc.x = fmaf(v0.x, m0, acc.x); acc.y = fmaf(v0.y, m0, acc.y);
                    acc.z = fmaf(v0.z, m0, acc.z); acc.w = fmaf(v0.w, m0, acc.w);
                    acc.x = fmaf(v1.x, m1, acc.x); acc.y = fmaf(v1.y, m1, acc.y);
                    acc.z = fmaf(v1.z, m1, acc.z); acc.w = fmaf(v1.w, m1, acc.w);
                    acc.x = fmaf(v2.x, m2, acc.x); acc.y = fmaf(v2.y, m2, acc.y);
                    acc.z = fmaf(v2.z, m2, acc.z); acc.w = fmaf(v2.w, m2, acc.w);
                    acc.x = fmaf(v3.x, m3, acc.x); acc.y = fmaf(v3.y, m3, acc.y);
                    acc.z = fmaf(v3.z, m3, acc.z); acc.w = fmaf(v3.w, m3, acc.w);
                }
                e += cnt;
            }
        }
        As[(lane * 4 + 0) * 64 + m] = acc.x;
        As[(lane * 4 + 1) * 64 + m] = acc.y;
        As[(lane * 4 + 2) * 64 + m] = acc.z;
        As[(lane * 4 + 3) * 64 + m] = acc.w;
    }
    __syncthreads();

    // ---- GEMM: micro-tile 4 rows x 8 cols, packed f32x2 accumulators
    int tn = tid & 15;   // cols tn*8 .. +7
    int tm = tid >> 4;   // rows tm*4 .. +3

    u64 acc2[4][4];
    #pragma unroll
    for (int i = 0; i < 4; i++)
        #pragma unroll
        for (int jj = 0; jj < 4; jj++) acc2[i][jj] = 0ull;

    #pragma unroll 4
    for (int k = 0; k < HID; k++) {
        float4 a = *(const float4*)&As[k * 64 + tm * 4];
        const u64* wrow = (const u64*)&Ws[k * HID + tn * 8];
        u64 b0 = wrow[0], b1 = wrow[1], b2 = wrow[2], b3 = wrow[3];
        u64 a0 = pack2(a.x), a1 = pack2(a.y), a2 = pack2(a.z), a3 = pack2(a.w);
        fma2(acc2[0][0], a0, b0); fma2(acc2[0][1], a0, b1);
        fma2(acc2[0][2], a0, b2); fma2(acc2[0][3], a0, b3);
        fma2(acc2[1][0], a1, b0); fma2(acc2[1][1], a1, b1);
        fma2(acc2[1][2], a1, b2); fma2(acc2[1][3], a1, b3);
        fma2(acc2[2][0], a2, b0); fma2(acc2[2][1], a2, b1);
        fma2(acc2[2][2], a2, b2); fma2(acc2[2][3], a2, b3);
        fma2(acc2[3][0], a3, b0); fma2(acc2[3][1], a3, b1);
        fma2(acc2[3][2], a3, b2); fma2(acc2[3][3], a3, b3);
    }

    // ---- Epilogue: bias, ReLU, residual, LayerNorm (16-lane shuffle reduce)
    int c0 = tn * 8;
    float bb[8], gg[8], be[8];
    {
        float4 t0 = *(const float4*)&bias[c0],  t1 = *(const float4*)&bias[c0 + 4];
        bb[0]=t0.x; bb[1]=t0.y; bb[2]=t0.z; bb[3]=t0.w; bb[4]=t1.x; bb[5]=t1.y; bb[6]=t1.z; bb[7]=t1.w;
        float4 g0 = *(const float4*)&gamma[c0], g1 = *(const float4*)&gamma[c0 + 4];
        gg[0]=g0.x; gg[1]=g0.y; gg[2]=g0.z; gg[3]=g0.w; gg[4]=g1.x; gg[5]=g1.y; gg[6]=g1.z; gg[7]=g1.w;
        float4 e0 = *(const float4*)&beta[c0],  e1 = *(const float4*)&beta[c0 + 4];
        be[0]=e0.x; be[1]=e0.y; be[2]=e0.z; be[3]=e0.w; be[4]=e1.x; be[5]=e1.y; be[6]=e1.z; be[7]=e1.w;
    }

    #pragma unroll
    for (int i = 0; i < 4; i++) {
        int row = rowBase + tm * 4 + i;
        bool valid = row < N_NODES;
        int rowc = valid ? row : 0;

        float av[8];
        #pragma unroll
        for (int jj = 0; jj < 4; jj++) unpack2(acc2[i][jj], av[2 * jj], av[2 * jj + 1]);

        const float4* xr = (const float4*)&x[(size_t)rowc * HID + c0];
        float4 x0 = xr[0], x1 = xr[1];
        float xv[8] = {x0.x, x0.y, x0.z, x0.w, x1.x, x1.y, x1.z, x1.w};

        float v[8];
        float sum = 0.f, sq = 0.f;
        #pragma unroll
        for (int j = 0; j < 8; j++) {
            float t = fmaxf(av[j] + bb[j], 0.f) + xv[j];
            v[j] = t;
            sum += t;
            sq  += t * t;
        }
        #pragma unroll
        for (int off = 8; off > 0; off >>= 1) {
            sum += __shfl_xor_sync(0xffffffffu, sum, off, 16);
            sq  += __shfl_xor_sync(0xffffffffu, sq,  off, 16);
        }
        float mu   = sum * (1.f / HID);
        float var  = sq * (1.f / HID) - mu * mu;
        float rstd = rsqrtf(var + 1e-8f);

        if (valid) {
            float o[8];
            #pragma unroll
            for (int j = 0; j < 8; j++)
                o[j] = (v[j] - mu) * rstd * gg[j] + be[j];
            float4* op = (float4*)&out[(size_t)row * HID + c0];
            op[0] = make_float4(o[0], o[1], o[2], o[3]);
            op[1] = make_float4(o[4], o[5], o[6], o[7]);
        }
    }
}

// ---------------------------------------------------------------------------
extern "C" void kernel_launch(void* const* d_in, const int* in_sizes, int n_in,
                              void* d_out, int out_size) {
    const float* x     = (const float*)d_in[0];
    const int*   ei    = (const int*)d_in[1];
    const float* W     = (const float*)d_in[2];
    const float* b     = (const float*)d_in[3];
    const float* gamma = (const float*)d_in[4];
    const float* beta  = (const float*)d_in[5];
    float* out = (float*)d_out;

    const int* src = ei;             // edge_index[0]
    const int* dst = ei + N_EDGES;   // edge_index[1]

    void* degi_ptr = nullptr;
    void* cursor_ptr = nullptr;
    cudaGetSymbolAddress(&degi_ptr, g_degi);
    cudaGetSymbolAddress(&cursor_ptr, g_cursor);
    cudaMemsetAsync(degi_ptr, 0, N_NODES * sizeof(int));
    cudaMemsetAsync(cursor_ptr, 0, sizeof(int));

    k_count<<<(N_EDGES + 255) / 256, 256>>>(dst);
    k_alloc<<<(N_NODES + 255) / 256, 256>>>();
    k_fill<<<(N_EDGES + 255) / 256, 256>>>(src, dst);

    int smem = (HID * HID + HID * 64) * sizeof(float);
    cudaFuncSetAttribute(k_fused, cudaFuncAttributeMaxDynamicSharedMemorySize, smem);
    k_fused<<<(N_NODES + 63) / 64, 256, smem>>>(W, b, gamma, beta, x, out);
}